// round 17
// baseline (speedup 1.0000x reference)
#include <cuda_runtime.h>
#include <cuda_fp16.h>
#include <cstdint>

#define BATCH 8
#define EDGES 16384
#define C0 128
#define C1 256
#define OUTC 256
#define NEG 0.01f
#define BN_EPS_ 1e-5f

__device__ __half g_W0h[OUTC * 6 * C0];
__device__ __half g_W1h[OUTC * 6 * C1];   // BN-folded
__device__ float g_xt[(size_t)BATCH * EDGES * C0];
__device__ float g_at[(size_t)BATCH * EDGES * C1];   // lrelu(h0), pre-BN, E-major
__device__ float g_sum1[OUTC], g_sum2[OUTC], g_scale[OUTC], g_shift[OUTC], g_bias[OUTC];

__device__ __forceinline__ uint32_t smem_u32(const void* p) {
    uint32_t a;
    asm("{ .reg .u64 t; cvta.to.shared.u64 t, %1; cvt.u32.u64 %0, t; }" : "=r"(a) : "l"(p));
    return a;
}
__device__ __forceinline__ uint32_t sw64(uint32_t x) { return x ^ ((x >> 3) & 0x30); }
__device__ __forceinline__ void cpa16(uint32_t s, const void* g) {
    asm volatile("cp.async.cg.shared.global [%0], [%1], 16;" :: "r"(s), "l"(g));
}
__device__ __forceinline__ void cpa_commit() { asm volatile("cp.async.commit_group;"); }
__device__ __forceinline__ void ldsm4(uint32_t* r, uint32_t addr) {
    asm volatile("ldmatrix.sync.aligned.m8n8.x4.shared.b16 {%0,%1,%2,%3}, [%4];"
                 : "=r"(r[0]), "=r"(r[1]), "=r"(r[2]), "=r"(r[3]) : "r"(addr));
}
__device__ __forceinline__ void mma16816(float* d, const uint32_t* a, uint32_t b0, uint32_t b1) {
    asm volatile(
        "mma.sync.aligned.m16n8k16.row.col.f32.f16.f16.f32 "
        "{%0,%1,%2,%3}, {%4,%5,%6,%7}, {%8,%9}, {%0,%1,%2,%3};"
        : "+f"(d[0]), "+f"(d[1]), "+f"(d[2]), "+f"(d[3])
        : "r"(a[0]), "r"(a[1]), "r"(a[2]), "r"(a[3]), "r"(b0), "r"(b1));
}
__device__ __forceinline__ uint32_t pack_h2(float a, float b) {
    __half2 h = __float22half2_rn(make_float2(a, b));
    return *reinterpret_cast<uint32_t*>(&h);
}
__device__ __forceinline__ uint2 pack_h4(float4 v) {
    return make_uint2(pack_h2(v.x, v.y), pack_h2(v.z, v.w));
}

__global__ void zero_sums() {
    g_sum1[threadIdx.x] = 0.f;
    g_sum2[threadIdx.x] = 0.f;
}

// K-order: kp = 96b+32p+q; c = 16b+(q&15); jp = 2p+(q>>4); jp: f0,x1,x2,x3,x4,x6
template <int MODE>
__global__ void prep_wh(const float* __restrict__ W) {
    constexpr int C = MODE ? C1 : C0;
    constexpr int K = 6 * C;
    __half* Wh = MODE ? g_W1h : g_W0h;
    int i = blockIdx.x * blockDim.x + threadIdx.x;
    if (i < OUTC * K) {
        int kp = i % K, o = i / K;
        int b = kp / 96, rem = kp % 96;
        int p = rem >> 5, q = rem & 31;
        int c = 16 * b + (q & 15);
        int jp = 2 * p + (q >> 4);
        int jorig = (jp == 5) ? 6 : jp;
        const float* wr = W + (size_t)o * (7 * C) + c * 7;
        float v = wr[jorig];
        if (jp == 1 || jp == 2) v += wr[5];
        if (MODE) {
            float s = g_scale[c];
            v *= (jp <= 2) ? s : ((jp <= 4) ? fabsf(s) : s * s);
        }
        Wh[(size_t)o * K + kp] = __float2half(v);
    }
}

__global__ void bias_k(const float* __restrict__ W1) {
    int o = blockIdx.x, c = threadIdx.x;
    const float* w = W1 + (size_t)o * (7 * C1) + c * 7;
    __shared__ float red[256];
    red[c] = g_shift[c] * (w[0] + 2.f * (w[1] + w[2]) + 4.f * w[5]);
    __syncthreads();
    for (int s = 128; s; s >>= 1) {
        if (c < s) red[c] += red[c + s];
        __syncthreads();
    }
    if (c == 0) g_bias[o] = red[0];
}

__global__ void transpose_x(const float* __restrict__ x) {
    __shared__ float tile[32][33];
    int b = blockIdx.z, e0 = blockIdx.x * 32, c0 = blockIdx.y * 32;
    int tx = threadIdx.x, ty = threadIdx.y;
#pragma unroll
    for (int i = 0; i < 32; i += 8)
        tile[ty + i][tx] = x[((size_t)b * C0 + (c0 + ty + i)) * EDGES + e0 + tx];
    __syncthreads();
#pragma unroll
    for (int i = 0; i < 32; i += 8)
        g_xt[((size_t)b * EDGES + (e0 + ty + i)) * C0 + c0 + tx] = tile[tx][ty + i];
}

// smem: RAW 3x40960 @0 | A 4x8192 @122880 | W 4x16384 @155648 | gemS @221184
#define RAWSZ 40960u
#define AOFF 122880u
#define WOFF 155648u
#define GEMOFF 221184u
#define FUSED_SMEM 223232

template <int MODE>
__global__ __launch_bounds__(512, 1) void gemm_fused(float* __restrict__ outp,
                                                     const int* __restrict__ gem) {
    constexpr int C = MODE ? C1 : C0;
    constexpr int NBLK = C / 16;
    constexpr int T = 3 * NBLK;
    constexpr int K = 6 * C;
    const float* __restrict__ src = MODE ? g_at : g_xt;
    const __half* __restrict__ Wh = MODE ? g_W1h : g_W0h;

    extern __shared__ __align__(1024) char smemc[];
    uint32_t sb = smem_u32(smemc);
    const int tid = threadIdx.x, wid = tid >> 5, lane = tid & 31;
    const int wm = wid & 3, wn = wid >> 2;   // 4 M-groups x 4 N-groups, 32x64 tiles
    const int eCTA = (blockIdx.x & 127) * 128;
    const int bCTA = blockIdx.x >> 7;
    const float* __restrict__ srcB = src + (size_t)bCTA * EDGES * C;

    int* gemS = (int*)(smemc + GEMOFF);
    gemS[tid] = gem[((size_t)bCTA * EDGES + eCTA) * 4 + tid];
    __syncthreads();

    float acc[2][8][4];
#pragma unroll
    for (int i = 0; i < 2; i++)
#pragma unroll
        for (int j = 0; j < 8; j++)
#pragma unroll
            for (int k = 0; k < 4; k++) acc[i][j][k] = 0.f;

    const int lrW = tid >> 2, lcW = tid & 3;
    auto issueW = [&](int k) {
        uint32_t wd = sb + WOFF + (uint32_t)(k & 3) * 16384u;
        const __half* ws = Wh + k * 32 + (size_t)lrW * K + lcW * 8;
        cpa16(wd + sw64(lrW * 64 + lcW * 16), ws);
        cpa16(wd + sw64((lrW + 128) * 64 + lcW * 16), ws + (size_t)128 * K);
    };
    auto issueRawRow = [&](int blk, int r) {
        int e = tid >> 2, j = tid & 3;
        int rid = (r == 0) ? (eCTA + e) : gemS[e * 4 + (r - 1)];
        const float* sp = srcB + (size_t)rid * C + blk * 16 + j * 4;
        uint32_t d = sb + (uint32_t)(blk % 3) * RAWSZ + (uint32_t)r * 8192u +
                     (uint32_t)e * 64u + (uint32_t)j * 16u;
        cpa16(d, sp);
    };

#pragma unroll
    for (int r = 0; r < 5; r++) issueRawRow(0, r);
    issueW(0); cpa_commit();
#pragma unroll
    for (int r = 0; r < 5; r++) issueRawRow(1, r);
    issueW(1); cpa_commit();
    issueW(2); cpa_commit();

    const int lrow = lane & 15;
    const int lcol = (lane >> 4) * 16;

    for (int t = 0; t <= T; t++) {
        __syncthreads();
        if (t < T) {
            int b = t / 3, p = t - 3 * b;
            if (t >= 1 && t + 2 < T) issueW(t + 2);
            if (b + 2 < NBLK) {
                if (p == 0) { issueRawRow(b + 2, 0); issueRawRow(b + 2, 1); }
                else if (p == 1) { issueRawRow(b + 2, 2); issueRawRow(b + 2, 3); }
                else issueRawRow(b + 2, 4);
            }
            cpa_commit();
            asm volatile("cp.async.wait_group 3;");
        } else {
            asm volatile("cp.async.wait_group 0;");
        }
        __syncthreads();

        if (t < T && (t % 3) == 0) {
            // convert whole raw block -> A slots t,t+1,t+2; one unit = 4 channels of 1 edge
            int b = t / 3;
            const char* rawB = smemc + (size_t)(b % 3) * RAWSZ;
            char* A0 = smemc + AOFF + (size_t)(t & 3) * 8192;
            char* A1 = smemc + AOFF + (size_t)((t + 1) & 3) * 8192;
            char* A2 = smemc + AOFF + (size_t)((t + 2) & 3) * 8192;
            int e = tid >> 2, cg = tid & 3;
            const char* rb = rawB + e * 64 + cg * 16;
            float4 f0 = *(const float4*)(rb);
            float4 f1 = *(const float4*)(rb + 8192);
            float4 f2 = *(const float4*)(rb + 16384);
            float4 f3 = *(const float4*)(rb + 24576);
            float4 f4 = *(const float4*)(rb + 32768);
            float4 x1 = make_float4(f1.x + f3.x, f1.y + f3.y, f1.z + f3.z, f1.w + f3.w);
            float4 x2 = make_float4(f2.x + f4.x, f2.y + f4.y, f2.z + f4.z, f2.w + f4.w);
            float4 x3 = make_float4(fabsf(f1.x - f3.x), fabsf(f1.y - f3.y),
                                    fabsf(f1.z - f3.z), fabsf(f1.w - f3.w));
            float4 x4 = make_float4(fabsf(f2.x - f4.x), fabsf(f2.y - f4.y),
                                    fabsf(f2.z - f4.z), fabsf(f2.w - f4.w));
            float4 x6;
            {
                float avg, d1, d2, d3, d4;
                avg = 0.25f * (x1.x + x2.x);
                d1 = f1.x - avg; d2 = f2.x - avg; d3 = f3.x - avg; d4 = f4.x - avg;
                x6.x = d1 * d1 + d2 * d2 + d3 * d3 + d4 * d4;
                avg = 0.25f * (x1.y + x2.y);
                d1 = f1.y - avg; d2 = f2.y - avg; d3 = f3.y - avg; d4 = f4.y - avg;
                x6.y = d1 * d1 + d2 * d2 + d3 * d3 + d4 * d4;
                avg = 0.25f * (x1.z + x2.z);
                d1 = f1.z - avg; d2 = f2.z - avg; d3 = f3.z - avg; d4 = f4.z - avg;
                x6.z = d1 * d1 + d2 * d2 + d3 * d3 + d4 * d4;
                avg = 0.25f * (x1.w + x2.w);
                d1 = f1.w - avg; d2 = f2.w - avg; d3 = f3.w - avg; d4 = f4.w - avg;
                x6.w = d1 * d1 + d2 * d2 + d3 * d3 + d4 * d4;
            }
            uint32_t base = (uint32_t)(e * 64 + cg * 8);
            uint32_t offA = sw64(base);        // feature (2p) span
            uint32_t offB = sw64(base + 32);   // feature (2p+1) span
            *(uint2*)(A0 + offA) = pack_h4(f0);
            *(uint2*)(A0 + offB) = pack_h4(x1);
            *(uint2*)(A1 + offA) = pack_h4(x2);
            *(uint2*)(A1 + offB) = pack_h4(x3);
            *(uint2*)(A2 + offA) = pack_h4(x4);
            *(uint2*)(A2 + offB) = pack_h4(x6);
        }
        if (t >= 1) {  // MMA stage t-1, 32x64 warp tile
            int st = t - 1;
            uint32_t AHs = sb + AOFF + (uint32_t)(st & 3) * 8192u;
            uint32_t Ws = sb + WOFF + (uint32_t)(st & 3) * 16384u;
#pragma unroll
            for (int ks = 0; ks < 2; ks++) {
                int ko = ks * 32;
                uint32_t ah[2][4], bb[4][4];
#pragma unroll
                for (int mi = 0; mi < 2; mi++)
                    ldsm4(ah[mi], AHs + sw64((wm * 32 + mi * 16 + lrow) * 64 + ko + lcol));
#pragma unroll
                for (int nj = 0; nj < 4; nj++)
                    ldsm4(bb[nj], Ws + sw64((wn * 64 + nj * 16 + lrow) * 64 + ko + lcol));
#pragma unroll
                for (int mi = 0; mi < 2; mi++)
#pragma unroll
                    for (int nj = 0; nj < 4; nj++) {
                        mma16816(acc[mi][2 * nj], ah[mi], bb[nj][0], bb[nj][2]);
                        mma16816(acc[mi][2 * nj + 1], ah[mi], bb[nj][1], bb[nj][3]);
                    }
            }
        }
    }

    // ---------------- epilogue ----------------
    __syncthreads();
    float* buf = (float*)smemc;                    // [256][129]
    float* bs = (float*)(smemc + 256 * 129 * 4);   // 512 floats
    {
        int q = lane >> 2, idq = lane & 3;
#pragma unroll
        for (int mi = 0; mi < 2; mi++)
#pragma unroll
            for (int p = 0; p < 8; p++) {
                int e = wm * 32 + mi * 16 + q;
                int o = wn * 64 + p * 8 + idq * 2;
                buf[o * 129 + e] = acc[mi][p][0];
                buf[(o + 1) * 129 + e] = acc[mi][p][1];
                buf[o * 129 + e + 8] = acc[mi][p][2];
                buf[(o + 1) * 129 + e + 8] = acc[mi][p][3];
            }
    }
    if (MODE == 0) bs[tid] = 0.f;
    __syncthreads();

    if (MODE == 0) {
        // e-major pass: g_at = lrelu(h0), fused BN stats
        int eo = tid >> 6, j = tid & 63;
        float s1[4] = {0.f, 0.f, 0.f, 0.f}, s2[4] = {0.f, 0.f, 0.f, 0.f};
#pragma unroll 1
        for (int it = 0; it < 16; it++) {
            int e = it * 8 + eo;
            float* dst = g_at + ((size_t)bCTA * EDGES + eCTA + e) * C1;
#pragma unroll
            for (int k = 0; k < 4; k++) {
                int o = j + 64 * k;
                float v = buf[o * 129 + e];
                float a = v > 0.f ? v : NEG * v;
                dst[o] = a;
                s1[k] += a;
                s2[k] += a * a;
            }
        }
#pragma unroll
        for (int k = 0; k < 4; k++) {
            atomicAdd(&bs[j + 64 * k], s1[k]);
            atomicAdd(&bs[256 + j + 64 * k], s2[k]);
        }
        __syncthreads();
        if (tid < 256) {
            atomicAdd(&g_sum1[tid], bs[tid]);
            atomicAdd(&g_sum2[tid], bs[tid + 256]);
        }
    } else {
        // residual add: h0 = inv_lrelu(g_at), accumulate into buf
        {
            int e = tid >> 2, j = tid & 3;
            const float* at_row = g_at + ((size_t)bCTA * EDGES + eCTA + e) * C1 + j * 64;
#pragma unroll 4
            for (int i = 0; i < 16; i++) {
                float4 av = *(const float4*)(at_row + 4 * i);
                float h0 = av.x > 0.f ? av.x : av.x * 100.f;
                float h1 = av.y > 0.f ? av.y : av.y * 100.f;
                float h2 = av.z > 0.f ? av.z : av.z * 100.f;
                float h3 = av.w > 0.f ? av.w : av.w * 100.f;
                int o = j * 64 + 4 * i;
                buf[(o + 0) * 129 + e] += h0;
                buf[(o + 1) * 129 + e] += h1;
                buf[(o + 2) * 129 + e] += h2;
                buf[(o + 3) * 129 + e] += h3;
            }
        }
        __syncthreads();
        int o = tid >> 1, hh = (tid & 1) * 64;
        float bo = g_bias[o];
        const float* srow = buf + o * 129 + hh;
        size_t gbase = ((size_t)bCTA * OUTC + o) * EDGES + eCTA + hh;
#pragma unroll 4
        for (int i = 0; i < 16; i++) {
            float v0 = srow[4 * i] + bo, v1 = srow[4 * i + 1] + bo;
            float v2 = srow[4 * i + 2] + bo, v3 = srow[4 * i + 3] + bo;
            v0 = v0 > 0.f ? v0 : NEG * v0;
            v1 = v1 > 0.f ? v1 : NEG * v1;
            v2 = v2 > 0.f ? v2 : NEG * v2;
            v3 = v3 > 0.f ? v3 : NEG * v3;
            *(float4*)(outp + gbase + 4 * i) = make_float4(v0, v1, v2, v3);
        }
    }
}

__global__ void bn_finalize(const float* __restrict__ gamma, const float* __restrict__ beta) {
    int o = threadIdx.x;
    float n = (float)((size_t)BATCH * EDGES);
    float mean = g_sum1[o] / n;
    float var = g_sum2[o] / n - mean * mean;
    float sc = gamma[o] * rsqrtf(var + BN_EPS_);
    g_scale[o] = sc;
    g_shift[o] = beta[o] - mean * sc;
}

extern "C" void kernel_launch(void* const* d_in, const int* in_sizes, int n_in,
                              void* d_out, int out_size) {
    (void)in_sizes; (void)n_in; (void)out_size;
    const float* x     = (const float*)d_in[0];
    const int*   gem   = (const int*)d_in[1];
    const float* W0    = (const float*)d_in[2];
    const float* W1    = (const float*)d_in[3];
    const float* gamma = (const float*)d_in[4];
    const float* beta  = (const float*)d_in[5];
    float* out = (float*)d_out;

    cudaFuncSetAttribute(gemm_fused<0>, cudaFuncAttributeMaxDynamicSharedMemorySize, FUSED_SMEM);
    cudaFuncSetAttribute(gemm_fused<1>, cudaFuncAttributeMaxDynamicSharedMemorySize, FUSED_SMEM);

    // 4th launch = gemm_fused<0> (ncu sample target)
    zero_sums<<<1, 256>>>();
    transpose_x<<<dim3(EDGES / 32, C0 / 32, BATCH), dim3(32, 8)>>>(x);
    prep_wh<0><<<(OUTC * 6 * C0 + 255) / 256, 256>>>(W0);
    gemm_fused<0><<<BATCH * EDGES / 128, 512, FUSED_SMEM>>>(nullptr, gem);

    bn_finalize<<<1, 256>>>(gamma, beta);
    prep_wh<1><<<(OUTC * 6 * C1 + 255) / 256, 256>>>(W1);
    bias_k<<<256, 256>>>(W1);

    gemm_fused<1><<<BATCH * EDGES / 128, 512, FUSED_SMEM>>>(out, gem);
}